// round 4
// baseline (speedup 1.0000x reference)
#include <cuda_runtime.h>
#include <cuda_bf16.h>

// GRU scan: B=2048 sequences, T=2048 steps, D=3 input, H=32 hidden.
// Output out[b, t] = h[0] after step t (float32, B*T elements).
//
// Design: one warp per batch element. Lane j owns hidden unit j and keeps
// rows j, 32+j, 64+j of weight_hh (r/z/a gates) in registers (96 regs).
// Per step: h_k broadcast via __shfl_sync, 96 register-resident FFMAs.
// No shared memory, no syncs, fully graph-capturable single launch.

#define T_DIM 2048
#define B_DIM 2048
#define H_DIM 32

__device__ __forceinline__ float sigm_f(float x) {
    // 1 / (1 + e^-x); large |x| saturates correctly via inf/0.
    return __fdividef(1.0f, 1.0f + __expf(-x));
}

__device__ __forceinline__ float tanh_f(float x) {
    // tanh(x) = 1 - 2/(e^{2x}+1); saturates correctly at +-1 for large |x|.
    return 1.0f - __fdividef(2.0f, __expf(2.0f * x) + 1.0f);
}

__global__ void __launch_bounds__(128, 4)
gru_scan_kernel(const float* __restrict__ inp,      // [B, T, 3]
                const float* __restrict__ wih,      // [96, 3]
                const float* __restrict__ whh,      // [96, 32]
                const float* __restrict__ bias,     // [96]
                const float* __restrict__ bias_n,   // [32]
                float* __restrict__ out)            // [B, T]
{
    const int lane = threadIdx.x & 31;
    const int warp = threadIdx.x >> 5;
    const int b    = blockIdx.x * 4 + warp;

    // --- load weights for this lane's hidden unit into registers ---
    float wr[H_DIM], wz[H_DIM], wa[H_DIM];
#pragma unroll
    for (int k = 0; k < H_DIM; ++k) {
        wr[k] = whh[(      lane) * H_DIM + k];
        wz[k] = whh[(32 +  lane) * H_DIM + k];
        wa[k] = whh[(64 +  lane) * H_DIM + k];
    }
    const float wir0 = wih[lane * 3 + 0], wir1 = wih[lane * 3 + 1], wir2 = wih[lane * 3 + 2];
    const float wiz0 = wih[(32 + lane) * 3 + 0], wiz1 = wih[(32 + lane) * 3 + 1], wiz2 = wih[(32 + lane) * 3 + 2];
    const float wia0 = wih[(64 + lane) * 3 + 0], wia1 = wih[(64 + lane) * 3 + 1], wia2 = wih[(64 + lane) * 3 + 2];
    const float bir = bias[lane], biz = bias[32 + lane], bia = bias[64 + lane];
    const float bn  = bias_n[lane];

    const float* xp = inp + (size_t)b * T_DIM * 3;
    float*       op = out + (size_t)b * T_DIM;

    float h = 0.0f;
    // prefetch first x (all lanes read same address -> broadcast, 1 sector)
    float x0 = __ldg(xp + 0), x1 = __ldg(xp + 1), x2 = __ldg(xp + 2);

    for (int t = 0; t < T_DIM; ++t) {
        // input gates (uses current x), then prefetch next step's x so the
        // load latency overlaps the 96-FFMA hidden matvec below.
        float ir = fmaf(wir2, x2, fmaf(wir1, x1, fmaf(wir0, x0, bir)));
        float iz = fmaf(wiz2, x2, fmaf(wiz1, x1, fmaf(wiz0, x0, biz)));
        float ia = fmaf(wia2, x2, fmaf(wia1, x1, fmaf(wia0, x0, bia)));
        if (t + 1 < T_DIM) {
            const float* nx = xp + (size_t)(t + 1) * 3;
            x0 = __ldg(nx + 0);
            x1 = __ldg(nx + 1);
            x2 = __ldg(nx + 2);
        }

        // hidden gates: hg = h @ Whh^T, h_k broadcast via shuffle
        float hr = 0.0f, hz = 0.0f, ha = 0.0f;
#pragma unroll
        for (int k = 0; k < H_DIM; ++k) {
            float hk = __shfl_sync(0xffffffffu, h, k);
            hr = fmaf(wr[k], hk, hr);
            hz = fmaf(wz[k], hk, hz);
            ha = fmaf(wa[k], hk, ha);
        }

        float r = sigm_f(ir + hr);
        float z = sigm_f(iz + hz);
        float n = tanh_f(fmaf(r, ha, ia + bn));
        h = fmaf(z, h - n, n);   // (1-z)*n + z*h

        if (lane == 0) op[t] = h;   // emit hidden unit 0
    }
}

extern "C" void kernel_launch(void* const* d_in, const int* in_sizes, int n_in,
                              void* d_out, int out_size) {
    const float* inp    = (const float*)d_in[0];
    const float* wih    = (const float*)d_in[1];
    const float* whh    = (const float*)d_in[2];
    const float* bias   = (const float*)d_in[3];
    const float* bias_n = (const float*)d_in[4];
    float* out = (float*)d_out;

    // 4 warps per CTA, one warp per batch element -> 512 CTAs, 2048 warps.
    gru_scan_kernel<<<B_DIM / 4, 128>>>(inp, wih, whh, bias, bias_n, out);
}

// round 5
// speedup vs baseline: 1.3755x; 1.3755x over previous
#include <cuda_runtime.h>
#include <cuda_bf16.h>

// GRU scan: B=2048 sequences, T=2048 steps, D=3 input, H=32 hidden.
// out[b, t] = h[0] after step t.
//
// R5 design: one warp per batch element (2048 warps). Lane j owns hidden
// unit j; rows j, 32+j, 64+j of Whh live in registers as PACKED f32 pairs
// (k, k+1 contiguous -> no duplication, still 96 regs). Per step:
//   - lane stores h_j to a per-warp double-buffered smem slab (STS.32)
//   - __syncwarp, then 8x LDS.128 broadcast reads give all 32 h as packed pairs
//   - 48x fma.rn.f32x2 (instead of 96 FFMA) + 3 fold-adds per gate
// This removes all 32 SHFLs per step and halves matvec issue count.

#define T_DIM 2048
#define B_DIM 2048

__device__ __forceinline__ unsigned long long fma2(unsigned long long a,
                                                   unsigned long long b,
                                                   unsigned long long c) {
    unsigned long long d;
    asm("fma.rn.f32x2 %0, %1, %2, %3;" : "=l"(d) : "l"(a), "l"(b), "l"(c));
    return d;
}

__device__ __forceinline__ float foldadd(unsigned long long p) {
    unsigned int lo, hi;
    asm("mov.b64 {%0, %1}, %2;" : "=r"(lo), "=r"(hi) : "l"(p));
    return __int_as_float(lo) + __int_as_float(hi);
}

__device__ __forceinline__ float sigm_f(float x) {
    return __fdividef(1.0f, 1.0f + __expf(-x));
}

__device__ __forceinline__ float tanh_f(float x) {
    return 1.0f - __fdividef(2.0f, __expf(2.0f * x) + 1.0f);
}

__global__ void __launch_bounds__(128, 4)
gru_scan_kernel(const float* __restrict__ inp,      // [B, T, 3]
                const float* __restrict__ wih,      // [96, 3]
                const float* __restrict__ whh,      // [96, 32]
                const float* __restrict__ bias,     // [96]
                const float* __restrict__ bias_n,   // [32]
                float* __restrict__ out)            // [B, T]
{
    const int lane = threadIdx.x & 31;
    const int warp = threadIdx.x >> 5;
    const int b    = blockIdx.x * 4 + warp;

    // per-warp double-buffered h slab; 16B-aligned for LDS.128 broadcasts
    __shared__ __align__(16) float hbuf[4][2][32];

    // --- weights for this lane's hidden unit, stored as packed f32 pairs ---
    unsigned long long wr[16], wz[16], wa[16];
    {
        const unsigned long long* r0 =
            reinterpret_cast<const unsigned long long*>(whh + (size_t)(lane) * 32);
        const unsigned long long* r1 =
            reinterpret_cast<const unsigned long long*>(whh + (size_t)(32 + lane) * 32);
        const unsigned long long* r2 =
            reinterpret_cast<const unsigned long long*>(whh + (size_t)(64 + lane) * 32);
#pragma unroll
        for (int i = 0; i < 16; ++i) { wr[i] = r0[i]; wz[i] = r1[i]; wa[i] = r2[i]; }
    }
    const float wir0 = wih[lane * 3 + 0], wir1 = wih[lane * 3 + 1], wir2 = wih[lane * 3 + 2];
    const float wiz0 = wih[(32 + lane) * 3 + 0], wiz1 = wih[(32 + lane) * 3 + 1], wiz2 = wih[(32 + lane) * 3 + 2];
    const float wia0 = wih[(64 + lane) * 3 + 0], wia1 = wih[(64 + lane) * 3 + 1], wia2 = wih[(64 + lane) * 3 + 2];
    const float bir = bias[lane], biz = bias[32 + lane];
    const float bia = bias[64 + lane] + bias_n[lane];   // fold bias_n into a-gate bias

    const float* xp = inp + (size_t)b * T_DIM * 3;
    float*       op = out + (size_t)b * T_DIM;

    float h = 0.0f;
    float x0 = __ldg(xp + 0), x1 = __ldg(xp + 1), x2 = __ldg(xp + 2);

    for (int t = 0; t < T_DIM; ++t) {
        // input gates for current x; prefetch next x to overlap the matvec
        float ir = fmaf(wir2, x2, fmaf(wir1, x1, fmaf(wir0, x0, bir)));
        float iz = fmaf(wiz2, x2, fmaf(wiz1, x1, fmaf(wiz0, x0, biz)));
        float ia = fmaf(wia2, x2, fmaf(wia1, x1, fmaf(wia0, x0, bia)));
        if (t + 1 < T_DIM) {
            const float* nx = xp + (size_t)(t + 1) * 3;
            x0 = __ldg(nx + 0);
            x1 = __ldg(nx + 1);
            x2 = __ldg(nx + 2);
        }

        // publish h_j, then broadcast-read all 32 h as packed pairs.
        // Double-buffered slot: the data dependence (h_{t+1} consumes LDS(t))
        // guarantees slot t&1 is fully read before it is rewritten at t+2,
        // so ONE syncwarp per step is sufficient.
        const int slot = t & 1;
        hbuf[warp][slot][lane] = h;
        __syncwarp();

        unsigned long long ar = 0ull, az = 0ull, aa = 0ull;
        const ulonglong2* hp =
            reinterpret_cast<const ulonglong2*>(&hbuf[warp][slot][0]);
#pragma unroll
        for (int i = 0; i < 8; ++i) {
            ulonglong2 v = hp[i];           // LDS.128 broadcast: pairs (2i*2 .. )
            ar = fma2(wr[2 * i],     v.x, ar);
            az = fma2(wz[2 * i],     v.x, az);
            aa = fma2(wa[2 * i],     v.x, aa);
            ar = fma2(wr[2 * i + 1], v.y, ar);
            az = fma2(wz[2 * i + 1], v.y, az);
            aa = fma2(wa[2 * i + 1], v.y, aa);
        }
        float hr = foldadd(ar);
        float hz = foldadd(az);
        float ha = foldadd(aa);

        float r = sigm_f(ir + hr);
        float z = sigm_f(iz + hz);
        float n = tanh_f(fmaf(r, ha, ia));
        h = fmaf(z, h - n, n);              // (1-z)*n + z*h

        if (lane == 0) op[t] = h;
    }
}

extern "C" void kernel_launch(void* const* d_in, const int* in_sizes, int n_in,
                              void* d_out, int out_size) {
    const float* inp    = (const float*)d_in[0];
    const float* wih    = (const float*)d_in[1];
    const float* whh    = (const float*)d_in[2];
    const float* bias   = (const float*)d_in[3];
    const float* bias_n = (const float*)d_in[4];
    float* out = (float*)d_out;

    gru_scan_kernel<<<B_DIM / 4, 128>>>(inp, wih, whh, bias, bias_n, out);
}

// round 6
// speedup vs baseline: 1.5626x; 1.1360x over previous
#include <cuda_runtime.h>
#include <cuda_bf16.h>

// GRU scan: B=2048 sequences, T=2048 steps, D=3 input, H=32 hidden.
// out[b, t] = h[0] after step t.
//
// R6 design: each warp processes TWO adjacent batch elements packed as
// f32x2 (batch pair in the two halves of a 64-bit register). Lane j owns
// hidden unit j for both batches. Whh rows j/32+j/64+j are kept in registers
// DUPLICATED into both f32x2 halves (96 u64 = 192 regs), so the matvec is
// 96 fma.rn.f32x2 per step covering both batches, and the per-gate
// accumulators stay batch-packed -> no fold adds.
// h exchange: one STS.64 per lane + 16 broadcast LDS.128 per step.
// 1024 warps (grid 256 x 128 thr), __launch_bounds__(128,2) -> 256-reg
// budget, eliminating the R5 spills.

#define T_DIM 2048
#define B_DIM 2048

typedef unsigned long long u64;

__device__ __forceinline__ u64 fma2(u64 a, u64 b, u64 c) {
    u64 d;
    asm("fma.rn.f32x2 %0, %1, %2, %3;" : "=l"(d) : "l"(a), "l"(b), "l"(c));
    return d;
}

__device__ __forceinline__ u64 pack2(float a, float b) {
    u64 d;
    asm("mov.b64 %0, {%1, %2};" : "=l"(d) : "f"(a), "f"(b));
    return d;
}

__device__ __forceinline__ void unpack2(u64 p, float& a, float& b) {
    asm("mov.b64 {%0, %1}, %2;" : "=f"(a), "=f"(b) : "l"(p));
}

__device__ __forceinline__ float sigm_f(float x) {
    return __fdividef(1.0f, 1.0f + __expf(-x));
}

__device__ __forceinline__ float tanh_f(float x) {
    return 1.0f - __fdividef(2.0f, __expf(2.0f * x) + 1.0f);
}

__global__ void __launch_bounds__(128, 2)
gru_scan_kernel(const float* __restrict__ inp,      // [B, T, 3]
                const float* __restrict__ wih,      // [96, 3]
                const float* __restrict__ whh,      // [96, 32]
                const float* __restrict__ bias,     // [96]
                const float* __restrict__ bias_n,   // [32]
                float* __restrict__ out)            // [B, T]
{
    const int lane = threadIdx.x & 31;
    const int warp = threadIdx.x >> 5;
    const int bp   = blockIdx.x * 4 + warp;     // batch-pair index (0..1023)
    const int b0   = 2 * bp;                    // handles batches b0, b0+1

    // per-warp double-buffered packed-h slab; 16B-aligned for LDS.128
    __shared__ __align__(16) u64 hbuf[4][2][32];

    // --- Whh rows for this lane, duplicated into both f32x2 halves ---
    u64 wr[32], wz[32], wa[32];
#pragma unroll
    for (int k = 0; k < 32; ++k) {
        float r = whh[(      lane) * 32 + k];
        float z = whh[(32 +  lane) * 32 + k];
        float a = whh[(64 +  lane) * 32 + k];
        wr[k] = pack2(r, r);
        wz[k] = pack2(z, z);
        wa[k] = pack2(a, a);
    }
    const float wir0 = wih[lane * 3 + 0], wir1 = wih[lane * 3 + 1], wir2 = wih[lane * 3 + 2];
    const float wiz0 = wih[(32 + lane) * 3 + 0], wiz1 = wih[(32 + lane) * 3 + 1], wiz2 = wih[(32 + lane) * 3 + 2];
    const float wia0 = wih[(64 + lane) * 3 + 0], wia1 = wih[(64 + lane) * 3 + 1], wia2 = wih[(64 + lane) * 3 + 2];
    const float bir = bias[lane], biz = bias[32 + lane];
    const float bia = bias[64 + lane] + bias_n[lane];   // bias_n folded into a-gate

    // batch b0+1 is at a fixed offset from b0: +T*3 floats (x), +T floats (out)
    const float* xp = inp + (size_t)b0 * T_DIM * 3;
    float*       op = out + (size_t)b0 * T_DIM;

    float ha = 0.0f, hb = 0.0f;   // hidden unit `lane` of batch b0 / b0+1
    float xa0 = __ldg(xp + 0),            xa1 = __ldg(xp + 1),            xa2 = __ldg(xp + 2);
    float xb0 = __ldg(xp + T_DIM * 3 + 0), xb1 = __ldg(xp + T_DIM * 3 + 1), xb2 = __ldg(xp + T_DIM * 3 + 2);

    for (int t = 0; t < T_DIM; ++t) {
        // scalar input gates for both batches (shared weight regs)
        float ira = fmaf(wir2, xa2, fmaf(wir1, xa1, fmaf(wir0, xa0, bir)));
        float iza = fmaf(wiz2, xa2, fmaf(wiz1, xa1, fmaf(wiz0, xa0, biz)));
        float iaa = fmaf(wia2, xa2, fmaf(wia1, xa1, fmaf(wia0, xa0, bia)));
        float irb = fmaf(wir2, xb2, fmaf(wir1, xb1, fmaf(wir0, xb0, bir)));
        float izb = fmaf(wiz2, xb2, fmaf(wiz1, xb1, fmaf(wiz0, xb0, biz)));
        float iab = fmaf(wia2, xb2, fmaf(wia1, xb1, fmaf(wia0, xb0, bia)));
        {   // prefetch next step's x for both batches (clamped, branch-free)
            int tn = (t + 1 < T_DIM) ? (t + 1) : t;
            const float* nx = xp + (size_t)tn * 3;
            xa0 = __ldg(nx + 0);             xa1 = __ldg(nx + 1);             xa2 = __ldg(nx + 2);
            xb0 = __ldg(nx + T_DIM * 3 + 0); xb1 = __ldg(nx + T_DIM * 3 + 1); xb2 = __ldg(nx + T_DIM * 3 + 2);
        }

        // publish packed h, broadcast-read all 32 packed h values.
        // Double-buffered slot: data dependence guarantees slot t&1 is fully
        // read before being rewritten at t+2 -> one syncwarp per step.
        const int slot = t & 1;
        hbuf[warp][slot][lane] = pack2(ha, hb);
        __syncwarp();

        u64 ar = 0ull, az = 0ull, aa = 0ull;
        const ulonglong2* hp =
            reinterpret_cast<const ulonglong2*>(&hbuf[warp][slot][0]);
#pragma unroll
        for (int i = 0; i < 16; ++i) {
            ulonglong2 v = hp[i];               // h2[2i], h2[2i+1] (broadcast)
            ar = fma2(wr[2 * i],     v.x, ar);
            az = fma2(wz[2 * i],     v.x, az);
            aa = fma2(wa[2 * i],     v.x, aa);
            ar = fma2(wr[2 * i + 1], v.y, ar);
            az = fma2(wz[2 * i + 1], v.y, az);
            aa = fma2(wa[2 * i + 1], v.y, aa);
        }
        float hra, hrb, hza, hzb, haa, hab;
        unpack2(ar, hra, hrb);
        unpack2(az, hza, hzb);
        unpack2(aa, haa, hab);

        // scalar activations per batch
        float ra = sigm_f(ira + hra);
        float za = sigm_f(iza + hza);
        float na = tanh_f(fmaf(ra, haa, iaa));
        ha = fmaf(za, ha - na, na);

        float rb = sigm_f(irb + hrb);
        float zb = sigm_f(izb + hzb);
        float nb = tanh_f(fmaf(rb, hab, iab));
        hb = fmaf(zb, hb - nb, nb);

        if (lane == 0) {
            op[t]         = ha;
            op[T_DIM + t] = hb;
        }
    }
}

extern "C" void kernel_launch(void* const* d_in, const int* in_sizes, int n_in,
                              void* d_out, int out_size) {
    const float* inp    = (const float*)d_in[0];
    const float* wih    = (const float*)d_in[1];
    const float* whh    = (const float*)d_in[2];
    const float* bias   = (const float*)d_in[3];
    const float* bias_n = (const float*)d_in[4];
    float* out = (float*)d_out;

    // 2 batches per warp, 4 warps per CTA -> 256 CTAs, 1024 warps.
    gru_scan_kernel<<<B_DIM / 8, 128>>>(inp, wih, whh, bias, bias_n, out);
}